// round 2
// baseline (speedup 1.0000x reference)
#include <cuda_runtime.h>
#include <math.h>
#include <stdint.h>

#define S_LEN 8192
#define LCC   16
#define DW    256
#define DC    64
#define HC    128
#define HH    512
#define T_TAGS 64
#define H2    256
#define KIN   384      /* HC + DW */
#define NBC   8        /* CTAs per direction (one portable cluster) */
#define RT2   512

/* ------------------- scratch (device globals; no allocation) ------------- */
__device__ float g_Xc[(size_t)LCC * S_LEN * 4 * HC];
__device__ int   g_charidx[LCC * S_LEN];
__device__ float g_gates[S_LEN * 4 * HC];
__device__ float g_Hc[S_LEN * HC];
__device__ float g_Cc[S_LEN * HC];
__device__ float g_charfeat[S_LEN * HC];
__device__ float g_embeds[S_LEN * KIN];
__device__ float g_Gf[(size_t)S_LEN * 4 * H2];
__device__ float g_Gb[(size_t)S_LEN * 4 * H2];
__device__ float g_lstm_out[S_LEN * HH];
__device__ float g_logits[S_LEN * T_TAGS];

__device__ __forceinline__ float sigf(float x) { return 1.0f / (1.0f + expf(-x)); }

/* ---- PTX helpers ---- */
__device__ __forceinline__ uint32_t smem_u32(const void* p) {
    uint32_t a;
    asm("{ .reg .u64 t; cvta.to.shared.u64 t, %1; cvt.u32.u64 %0, t; }" : "=r"(a) : "l"(p));
    return a;
}
__device__ __forceinline__ uint32_t mapa_rank(uint32_t addr, uint32_t rank) {
    uint32_t r;
    asm("mapa.shared::cluster.u32 %0, %1, %2;" : "=r"(r) : "r"(addr), "r"(rank));
    return r;
}
__device__ __forceinline__ void mbar_wait_cluster(uint32_t mbar, uint32_t parity) {
    uint32_t done;
    asm volatile(
        "{\n\t.reg .pred p;\n\t"
        "mbarrier.try_wait.parity.acquire.cluster.shared::cta.b64 p, [%1], %2;\n\t"
        "selp.b32 %0, 1, 0, p;\n\t}"
        : "=r"(done) : "r"(mbar), "r"(parity) : "memory");
    while (!done) {
        asm volatile(
            "{\n\t.reg .pred p;\n\t"
            "mbarrier.try_wait.parity.acquire.cluster.shared::cta.b64 p, [%1], %2, 0x989680;\n\t"
            "selp.b32 %0, 1, 0, p;\n\t}"
            : "=r"(done) : "r"(mbar), "r"(parity) : "memory");
    }
}
#define FMA2(acc, a, b) asm("fma.rn.f32x2 %0, %1, %2, %0;" : "+l"(acc) : "l"(a), "l"(b))
#define UNPACK2(lo, hi, v) asm("mov.b64 {%0,%1}, %2;" : "=f"(lo), "=f"(hi) : "l"(v))

/* ------------------- init: must run every launch (graph determinism) ----- */
__global__ void init_state() {
    int idx = blockIdx.x * blockDim.x + threadIdx.x;
    int stride = gridDim.x * blockDim.x;
    for (int i = idx; i < S_LEN * HC; i += stride) {
        g_Hc[i] = 0.0f;
        g_Cc[i] = 0.0f;
    }
}

__global__ void build_charidx(const int* __restrict__ charsets) {
    int idx = blockIdx.x * blockDim.x + threadIdx.x;
    if (idx >= LCC * S_LEN) return;
    int t = idx / S_LEN;
    int w = idx - t * S_LEN;
    g_charidx[idx] = charsets[w * LCC + t];
}

/* ------------------- generic fp32 GEMM (as round 0) ----------------------- */
__global__ void __launch_bounds__(256) gemm_tn(
    const float* __restrict__ A, int lda,
    const float* __restrict__ B,
    const float* __restrict__ bias,
    float* __restrict__ C, int M, int N, int K,
    const int* __restrict__ gidx, int rev)
{
    __shared__ float4 As4[16 * 16];
    __shared__ float4 Bs4[16 * 16];
    float* As = (float*)As4;
    float* Bs = (float*)Bs4;

    int tid = threadIdx.x;
    int m0 = blockIdx.y * 64, n0 = blockIdx.x * 64;
    int lm = tid >> 2;
    int kq = tid & 3;

    int mg = m0 + lm;
    int arow = gidx ? gidx[mg] : (rev ? (M - 1 - mg) : mg);
    const float* Ap = A + (size_t)arow * lda;
    const float* Bp = B + (size_t)(n0 + lm) * K;

    int ty = tid >> 4, tx = tid & 15;
    float acc[4][4];
#pragma unroll
    for (int i = 0; i < 4; i++)
#pragma unroll
        for (int j = 0; j < 4; j++) acc[i][j] = 0.0f;

    for (int k0 = 0; k0 < K; k0 += 16) {
        float4 a = *(const float4*)(Ap + k0 + kq * 4);
        float4 b = *(const float4*)(Bp + k0 + kq * 4);
        __syncthreads();
        As[(kq * 4 + 0) * 64 + lm] = a.x;
        As[(kq * 4 + 1) * 64 + lm] = a.y;
        As[(kq * 4 + 2) * 64 + lm] = a.z;
        As[(kq * 4 + 3) * 64 + lm] = a.w;
        Bs[(kq * 4 + 0) * 64 + lm] = b.x;
        Bs[(kq * 4 + 1) * 64 + lm] = b.y;
        Bs[(kq * 4 + 2) * 64 + lm] = b.z;
        Bs[(kq * 4 + 3) * 64 + lm] = b.w;
        __syncthreads();
#pragma unroll
        for (int kk = 0; kk < 16; kk++) {
            float4 av = As4[kk * 16 + ty];
            float4 bv = Bs4[kk * 16 + tx];
            acc[0][0] += av.x * bv.x; acc[0][1] += av.x * bv.y;
            acc[0][2] += av.x * bv.z; acc[0][3] += av.x * bv.w;
            acc[1][0] += av.y * bv.x; acc[1][1] += av.y * bv.y;
            acc[1][2] += av.y * bv.z; acc[1][3] += av.y * bv.w;
            acc[2][0] += av.z * bv.x; acc[2][1] += av.z * bv.y;
            acc[2][2] += av.z * bv.z; acc[2][3] += av.z * bv.w;
            acc[3][0] += av.w * bv.x; acc[3][1] += av.w * bv.y;
            acc[3][2] += av.w * bv.z; acc[3][3] += av.w * bv.w;
        }
    }
#pragma unroll
    for (int i = 0; i < 4; i++) {
        int m = m0 + ty * 4 + i;
        int n = n0 + tx * 4;
        float4 o;
        o.x = acc[i][0]; o.y = acc[i][1]; o.z = acc[i][2]; o.w = acc[i][3];
        if (bias) {
            o.x += bias[n + 0]; o.y += bias[n + 1];
            o.z += bias[n + 2]; o.w += bias[n + 3];
        }
        *(float4*)(C + (size_t)m * N + n) = o;
    }
}

/* ------------------- char LSTM pointwise update --------------------------- */
__global__ void char_update(const int* __restrict__ lengths, int t) {
    int idx = blockIdx.x * blockDim.x + threadIdx.x;
    if (idx >= S_LEN * HC) return;
    int w = idx / HC, u = idx - w * HC;
    const float* xrow = g_Xc + ((size_t)t * S_LEN + w) * (4 * HC);
    const float* grow = g_gates + (size_t)w * (4 * HC);
    float gi = grow[0 * HC + u] + xrow[0 * HC + u];
    float gf = grow[1 * HC + u] + xrow[1 * HC + u];
    float gg = grow[2 * HC + u] + xrow[2 * HC + u];
    float go = grow[3 * HC + u] + xrow[3 * HC + u];
    float c = g_Cc[idx];
    c = sigf(gf) * c + sigf(gi) * tanhf(gg);
    float h = sigf(go) * tanhf(c);
    g_Cc[idx] = c;
    g_Hc[idx] = h;
    if (t == lengths[w] - 1) g_charfeat[idx] = h;
}

/* ------------------- embeds = [charfeat | word_emb[sentence]] ------------- */
__global__ void build_embeds(const int* __restrict__ sentence,
                             const float* __restrict__ word_emb) {
    int idx = blockIdx.x * blockDim.x + threadIdx.x;
    if (idx >= S_LEN * KIN) return;
    int w = idx / KIN, j = idx - w * KIN;
    float v;
    if (j < HC) v = g_charfeat[w * HC + j];
    else        v = word_emb[(size_t)sentence[w] * DW + (j - HC)];
    g_embeds[idx] = v;
}

/* ------------------- cluster-based bi-directional recurrence --------------
 * grid = 16 CTAs = 2 portable clusters of 8 (one per direction).
 * CTA (d,b) owns h-units [32b, 32b+32). 512 threads:
 *   r_local = tid>>2 in [0,128) gate rows, seg = tid&3 splits k into 4.
 * Weights live in registers as packed f32x2 pairs; dot via fma.rn.f32x2.
 * h exchange: producing warp writes its 32 h values into ALL peer CTAs'
 * shared double buffer (st.shared::cluster) then remote
 * mbarrier.arrive.release.cluster. Consumers try_wait.parity.acquire.cluster
 * on their local mbarrier (256 expected arrivals = 8 CTAs x 32 lanes).     */
__global__ void __launch_bounds__(RT2, 1) __cluster_dims__(NBC, 1, 1)
recurrent_cluster(const float* __restrict__ WhhF, const float* __restrict__ WhhB)
{
    __shared__ __align__(16) float s_h[2][H2];
    __shared__ float s_gates[128];
    __shared__ __align__(8) unsigned long long s_mbar;

    int tid = threadIdx.x;
    int d = blockIdx.x >> 3;
    int b = blockIdx.x & 7;
    const float* Whh = d ? WhhB : WhhF;
    const float* G = d ? g_Gb : g_Gf;

    int r_local = tid >> 2;        /* 0..127 */
    int seg = tid & 3;             /* 0..3   */
    int ul = r_local >> 2;         /* 0..31  */
    int gk = r_local & 3;          /* i,f,g,o */
    int row = gk * H2 + b * 32 + ul;

    /* 64 weights per thread, packed as 32 f32x2 pairs */
    ulonglong2 w[16];
    const float* wrow = Whh + (size_t)row * H2;
#pragma unroll
    for (int j = 0; j < 16; j++)
        w[j] = *reinterpret_cast<const ulonglong2*>(wrow + (j * 4 + seg) * 4);

    if (tid < H2) { s_h[0][tid] = 0.0f; s_h[1][tid] = 0.0f; }
    uint32_t my_mbar = smem_u32(&s_mbar);
    if (tid == 0) {
        asm volatile("mbarrier.init.shared.b64 [%0], %1;" :: "r"(my_mbar), "r"(256) : "memory");
        asm volatile("fence.mbarrier_init.release.cluster;" ::: "memory");
    }
    __syncthreads();
    asm volatile("barrier.cluster.arrive.aligned;" ::: "memory");
    asm volatile("barrier.cluster.wait.aligned;" ::: "memory");

    uint32_t my_h[2];
    my_h[0] = smem_u32(&s_h[0][0]);
    my_h[1] = smem_u32(&s_h[1][0]);

    float c = 0.0f;
    float gin = 0.0f;
    if (seg == 0) gin = G[row];    /* prefetch t=0 */

    for (int t = 0; t < S_LEN; t++) {
        if (t > 0) mbar_wait_cluster(my_mbar, (t + 1) & 1);

        const float* hb = s_h[t & 1];
        unsigned long long acc0 = 0ull, acc1 = 0ull;
#pragma unroll
        for (int j = 0; j < 16; j++) {
            ulonglong2 hv = *reinterpret_cast<const ulonglong2*>(hb + (j * 4 + seg) * 4);
            FMA2(acc0, w[j].x, hv.x);
            FMA2(acc1, w[j].y, hv.y);
        }
        float a0, a1, a2, a3;
        UNPACK2(a0, a1, acc0);
        UNPACK2(a2, a3, acc1);
        float acc = (a0 + a1) + (a2 + a3);
        acc += __shfl_xor_sync(0xffffffffu, acc, 1);
        acc += __shfl_xor_sync(0xffffffffu, acc, 2);
        if (seg == 0) s_gates[r_local] = acc + gin;
        if (seg == 0 && t + 1 < S_LEN)
            gin = G[(size_t)(t + 1) * (4 * H2) + row];  /* prefetch next step */
        __syncthreads();

        if (tid < 32) {
            float gi = s_gates[tid * 4 + 0];
            float gf = s_gates[tid * 4 + 1];
            float gg = s_gates[tid * 4 + 2];
            float go = s_gates[tid * 4 + 3];
            c = sigf(gf) * c + sigf(gi) * tanhf(gg);
            float h = sigf(go) * tanhf(c);
            int outrow = d ? (S_LEN - 1 - t) : t;
            g_lstm_out[(size_t)outrow * HH + d * H2 + b * 32 + tid] = h;

            uint32_t dst = my_h[(t + 1) & 1] + (uint32_t)(b * 32 + tid) * 4u;
#pragma unroll
            for (int p = 0; p < NBC; p++) {
                uint32_t ra = mapa_rank(dst, (uint32_t)p);
                asm volatile("st.shared::cluster.f32 [%0], %1;" :: "r"(ra), "f"(h) : "memory");
            }
#pragma unroll
            for (int p = 0; p < NBC; p++) {
                uint32_t rb = mapa_rank(my_mbar, (uint32_t)p);
                asm volatile("mbarrier.arrive.release.cluster.shared::cluster.b64 _, [%0];"
                             :: "r"(rb) : "memory");
            }
        }
    }

    asm volatile("barrier.cluster.arrive.aligned;" ::: "memory");
    asm volatile("barrier.cluster.wait.aligned;" ::: "memory");
}

/* ------------------- log_softmax over 64 tags (one warp per word) --------- */
__global__ void logsoftmax_kernel(float* __restrict__ out) {
    int gt = blockIdx.x * blockDim.x + threadIdx.x;
    int warp = gt >> 5;
    int lane = gt & 31;
    if (warp >= S_LEN) return;
    const float* l = g_logits + (size_t)warp * T_TAGS;
    float a = l[lane], b = l[lane + 32];
    float m = fmaxf(a, b);
#pragma unroll
    for (int o = 16; o > 0; o >>= 1) m = fmaxf(m, __shfl_xor_sync(0xffffffffu, m, o));
    float s = expf(a - m) + expf(b - m);
#pragma unroll
    for (int o = 16; o > 0; o >>= 1) s += __shfl_xor_sync(0xffffffffu, s, o);
    float lse = m + logf(s);
    out[(size_t)warp * T_TAGS + lane] = a - lse;
    out[(size_t)warp * T_TAGS + lane + 32] = b - lse;
}

/* ------------------- launcher --------------------------------------------- */
extern "C" void kernel_launch(void* const* d_in, const int* in_sizes, int n_in,
                              void* d_out, int out_size) {
    const int*   sentence  = (const int*)d_in[0];
    const int*   charsets  = (const int*)d_in[1];
    const int*   lengths   = (const int*)d_in[2];
    const float* word_emb  = (const float*)d_in[3];
    const float* char_emb  = (const float*)d_in[4];
    const float* cWih      = (const float*)d_in[5];
    const float* cWhh      = (const float*)d_in[6];
    const float* cb        = (const float*)d_in[7];
    const float* fWih      = (const float*)d_in[8];
    const float* fWhh      = (const float*)d_in[9];
    const float* fb        = (const float*)d_in[10];
    const float* bWih      = (const float*)d_in[11];
    const float* bWhh      = (const float*)d_in[12];
    const float* bb        = (const float*)d_in[13];
    const float* outW      = (const float*)d_in[14];
    const float* outb      = (const float*)d_in[15];
    float* out = (float*)d_out;

    void *pXc, *pIdx, *pGates, *pHc, *pEmb, *pGf, *pGb, *pLout, *pLog;
    cudaGetSymbolAddress(&pXc, g_Xc);
    cudaGetSymbolAddress(&pIdx, g_charidx);
    cudaGetSymbolAddress(&pGates, g_gates);
    cudaGetSymbolAddress(&pHc, g_Hc);
    cudaGetSymbolAddress(&pEmb, g_embeds);
    cudaGetSymbolAddress(&pGf, g_Gf);
    cudaGetSymbolAddress(&pGb, g_Gb);
    cudaGetSymbolAddress(&pLout, g_lstm_out);
    cudaGetSymbolAddress(&pLog, g_logits);

    /* reset per-launch state (graph-replay determinism) */
    init_state<<<2048, 256>>>();

    /* char LSTM input projection for all (t,w): gather + GEMM */
    build_charidx<<<(LCC * S_LEN + 255) / 256, 256>>>(charsets);
    gemm_tn<<<dim3(4 * HC / 64, LCC * S_LEN / 64), 256>>>(
        char_emb, DC, cWih, cb, (float*)pXc,
        LCC * S_LEN, 4 * HC, DC, (const int*)pIdx, 0);

    /* char LSTM: 16 time steps, batched over S */
    for (int t = 0; t < LCC; t++) {
        gemm_tn<<<dim3(4 * HC / 64, S_LEN / 64), 256>>>(
            (const float*)pHc, HC, cWhh, nullptr, (float*)pGates,
            S_LEN, 4 * HC, HC, nullptr, 0);
        char_update<<<S_LEN * HC / 256, 256>>>(lengths, t);
    }

    /* embeds + main input projections */
    build_embeds<<<S_LEN * KIN / 256, 256>>>(sentence, word_emb);
    gemm_tn<<<dim3(4 * H2 / 64, S_LEN / 64), 256>>>(
        (const float*)pEmb, KIN, fWih, fb, (float*)pGf,
        S_LEN, 4 * H2, KIN, nullptr, 0);
    gemm_tn<<<dim3(4 * H2 / 64, S_LEN / 64), 256>>>(
        (const float*)pEmb, KIN, bWih, bb, (float*)pGb,
        S_LEN, 4 * H2, KIN, nullptr, 1);

    /* sequential bidirectional recurrence: 2 clusters of 8 CTAs */
    recurrent_cluster<<<2 * NBC, RT2>>>(fWhh, bWhh);

    /* output projection + log_softmax */
    gemm_tn<<<dim3(T_TAGS / 64, S_LEN / 64), 256>>>(
        (const float*)pLout, HH, outW, outb, (float*)pLog,
        S_LEN, T_TAGS, HH, nullptr, 0);
    logsoftmax_kernel<<<(S_LEN * 32 + 255) / 256, 256>>>(out);
}

// round 4
// speedup vs baseline: 1.6011x; 1.6011x over previous
#include <cuda_runtime.h>
#include <math.h>
#include <stdint.h>

#define S_LEN 8192
#define LCC   16
#define DW    256
#define DC    64
#define HC    128
#define HH    512
#define T_TAGS 64
#define H2    256
#define KIN   384      /* HC + DW */
#define NBC   8        /* CTAs per direction (one portable cluster) */
#define RT2   512

/* ------------------- scratch (device globals; no allocation) ------------- */
__device__ float g_Xc[(size_t)LCC * S_LEN * 4 * HC];
__device__ int   g_charidx[LCC * S_LEN];
__device__ float g_gates[S_LEN * 4 * HC];
__device__ float g_Hc[S_LEN * HC];
__device__ float g_Cc[S_LEN * HC];
__device__ float g_charfeat[S_LEN * HC];
__device__ float g_embeds[S_LEN * KIN];
__device__ float g_Gf[(size_t)S_LEN * 4 * H2];
__device__ float g_Gb[(size_t)S_LEN * 4 * H2];
__device__ float g_lstm_out[S_LEN * HH];
__device__ float g_logits[S_LEN * T_TAGS];

__device__ __forceinline__ float sigf(float x) { return 1.0f / (1.0f + expf(-x)); }

/* ---- PTX helpers ---- */
__device__ __forceinline__ uint32_t smem_u32(const void* p) {
    uint32_t a;
    asm("{ .reg .u64 t; cvta.to.shared.u64 t, %1; cvt.u32.u64 %0, t; }" : "=r"(a) : "l"(p));
    return a;
}
__device__ __forceinline__ uint32_t mapa_rank(uint32_t addr, uint32_t rank) {
    uint32_t r;
    asm("mapa.shared::cluster.u32 %0, %1, %2;" : "=r"(r) : "r"(addr), "r"(rank));
    return r;
}
#define FMA2(acc, a, b) asm("fma.rn.f32x2 %0, %1, %2, %0;" : "+l"(acc) : "l"(a), "l"(b))
#define UNPACK2(lo, hi, v) asm("mov.b64 {%0,%1}, %2;" : "=f"(lo), "=f"(hi) : "l"(v))

/* ------------------- init: must run every launch (graph determinism) ----- */
__global__ void init_state() {
    int idx = blockIdx.x * blockDim.x + threadIdx.x;
    int stride = gridDim.x * blockDim.x;
    for (int i = idx; i < S_LEN * HC; i += stride) {
        g_Hc[i] = 0.0f;
        g_Cc[i] = 0.0f;
    }
}

__global__ void build_charidx(const int* __restrict__ charsets) {
    int idx = blockIdx.x * blockDim.x + threadIdx.x;
    if (idx >= LCC * S_LEN) return;
    int t = idx / S_LEN;
    int w = idx - t * S_LEN;
    g_charidx[idx] = charsets[w * LCC + t];
}

/* ------------------- generic fp32 GEMM ------------------------------------ */
__global__ void __launch_bounds__(256) gemm_tn(
    const float* __restrict__ A, int lda,
    const float* __restrict__ B,
    const float* __restrict__ bias,
    float* __restrict__ C, int M, int N, int K,
    const int* __restrict__ gidx, int rev)
{
    __shared__ float4 As4[16 * 16];
    __shared__ float4 Bs4[16 * 16];
    float* As = (float*)As4;
    float* Bs = (float*)Bs4;

    int tid = threadIdx.x;
    int m0 = blockIdx.y * 64, n0 = blockIdx.x * 64;
    int lm = tid >> 2;
    int kq = tid & 3;

    int mg = m0 + lm;
    int arow = gidx ? gidx[mg] : (rev ? (M - 1 - mg) : mg);
    const float* Ap = A + (size_t)arow * lda;
    const float* Bp = B + (size_t)(n0 + lm) * K;

    int ty = tid >> 4, tx = tid & 15;
    float acc[4][4];
#pragma unroll
    for (int i = 0; i < 4; i++)
#pragma unroll
        for (int j = 0; j < 4; j++) acc[i][j] = 0.0f;

    for (int k0 = 0; k0 < K; k0 += 16) {
        float4 a = *(const float4*)(Ap + k0 + kq * 4);
        float4 b = *(const float4*)(Bp + k0 + kq * 4);
        __syncthreads();
        As[(kq * 4 + 0) * 64 + lm] = a.x;
        As[(kq * 4 + 1) * 64 + lm] = a.y;
        As[(kq * 4 + 2) * 64 + lm] = a.z;
        As[(kq * 4 + 3) * 64 + lm] = a.w;
        Bs[(kq * 4 + 0) * 64 + lm] = b.x;
        Bs[(kq * 4 + 1) * 64 + lm] = b.y;
        Bs[(kq * 4 + 2) * 64 + lm] = b.z;
        Bs[(kq * 4 + 3) * 64 + lm] = b.w;
        __syncthreads();
#pragma unroll
        for (int kk = 0; kk < 16; kk++) {
            float4 av = As4[kk * 16 + ty];
            float4 bv = Bs4[kk * 16 + tx];
            acc[0][0] += av.x * bv.x; acc[0][1] += av.x * bv.y;
            acc[0][2] += av.x * bv.z; acc[0][3] += av.x * bv.w;
            acc[1][0] += av.y * bv.x; acc[1][1] += av.y * bv.y;
            acc[1][2] += av.y * bv.z; acc[1][3] += av.y * bv.w;
            acc[2][0] += av.z * bv.x; acc[2][1] += av.z * bv.y;
            acc[2][2] += av.z * bv.z; acc[2][3] += av.z * bv.w;
            acc[3][0] += av.w * bv.x; acc[3][1] += av.w * bv.y;
            acc[3][2] += av.w * bv.z; acc[3][3] += av.w * bv.w;
        }
    }
#pragma unroll
    for (int i = 0; i < 4; i++) {
        int m = m0 + ty * 4 + i;
        int n = n0 + tx * 4;
        float4 o;
        o.x = acc[i][0]; o.y = acc[i][1]; o.z = acc[i][2]; o.w = acc[i][3];
        if (bias) {
            o.x += bias[n + 0]; o.y += bias[n + 1];
            o.z += bias[n + 2]; o.w += bias[n + 3];
        }
        *(float4*)(C + (size_t)m * N + n) = o;
    }
}

/* ------------------- char LSTM pointwise update --------------------------- */
__global__ void char_update(const int* __restrict__ lengths, int t) {
    int idx = blockIdx.x * blockDim.x + threadIdx.x;
    if (idx >= S_LEN * HC) return;
    int w = idx / HC, u = idx - w * HC;
    const float* xrow = g_Xc + ((size_t)t * S_LEN + w) * (4 * HC);
    const float* grow = g_gates + (size_t)w * (4 * HC);
    float gi = grow[0 * HC + u] + xrow[0 * HC + u];
    float gf = grow[1 * HC + u] + xrow[1 * HC + u];
    float gg = grow[2 * HC + u] + xrow[2 * HC + u];
    float go = grow[3 * HC + u] + xrow[3 * HC + u];
    float c = g_Cc[idx];
    c = sigf(gf) * c + sigf(gi) * tanhf(gg);
    float h = sigf(go) * tanhf(c);
    g_Cc[idx] = c;
    g_Hc[idx] = h;
    if (t == lengths[w] - 1) g_charfeat[idx] = h;
}

/* ------------------- embeds = [charfeat | word_emb[sentence]] ------------- */
__global__ void build_embeds(const int* __restrict__ sentence,
                             const float* __restrict__ word_emb) {
    int idx = blockIdx.x * blockDim.x + threadIdx.x;
    if (idx >= S_LEN * KIN) return;
    int w = idx / KIN, j = idx - w * KIN;
    float v;
    if (j < HC) v = g_charfeat[w * HC + j];
    else        v = word_emb[(size_t)sentence[w] * DW + (j - HC)];
    g_embeds[idx] = v;
}

/* ------------------- cluster-based bi-directional recurrence --------------
 * grid = 16 CTAs = 2 portable clusters of 8 (one per direction).
 * CTA (d,b) owns h-units [32b, 32b+32). 512 threads:
 *   r_local = tid>>2 in [0,128) gate rows, seg = tid&3 splits k into 4.
 * Weights in registers as packed f32x2; dot via fma.rn.f32x2.
 * Per step: hardware cluster barrier (arrive=release / wait=acquire) orders
 * the producers' st.shared::cluster h-pushes against peers' reads. Double-
 * buffered smem h by step parity. NO per-lane mbarrier arrivals.           */
__global__ void __launch_bounds__(RT2, 1) __cluster_dims__(NBC, 1, 1)
recurrent_cluster(const float* __restrict__ WhhF, const float* __restrict__ WhhB)
{
    __shared__ __align__(16) float s_h[2][H2];
    __shared__ float s_gates[128];

    int tid = threadIdx.x;
    int d = blockIdx.x >> 3;
    int b = blockIdx.x & 7;
    const float* Whh = d ? WhhB : WhhF;
    const float* G = d ? g_Gb : g_Gf;

    int r_local = tid >> 2;        /* 0..127 */
    int seg = tid & 3;             /* 0..3   */
    int ul = r_local >> 2;         /* 0..31  */
    int gk = r_local & 3;          /* i,f,g,o */
    int row = gk * H2 + b * 32 + ul;

    /* 64 weights per thread, packed as 32 f32x2 pairs */
    ulonglong2 w[16];
    const float* wrow = Whh + (size_t)row * H2;
#pragma unroll
    for (int j = 0; j < 16; j++)
        w[j] = *reinterpret_cast<const ulonglong2*>(wrow + (j * 4 + seg) * 4);

    if (tid < H2) { s_h[0][tid] = 0.0f; s_h[1][tid] = 0.0f; }

    /* precompute remote destinations for this producer lane */
    uint32_t rdst[2][NBC];
    if (tid < 32) {
        uint32_t d0 = smem_u32(&s_h[0][b * 32 + tid]);
        uint32_t d1 = smem_u32(&s_h[1][b * 32 + tid]);
#pragma unroll
        for (int p = 0; p < NBC; p++) {
            rdst[0][p] = mapa_rank(d0, (uint32_t)p);
            rdst[1][p] = mapa_rank(d1, (uint32_t)p);
        }
    }
    __syncthreads();
    asm volatile("barrier.cluster.arrive.aligned;" ::: "memory");
    asm volatile("barrier.cluster.wait.aligned;" ::: "memory");

    float c = 0.0f;
    float gin = 0.0f;
    if (seg == 0) gin = G[row];    /* prefetch t=0 */

    for (int t = 0; t < S_LEN; t++) {
        const float* hb = s_h[t & 1];
        unsigned long long acc0 = 0ull, acc1 = 0ull;
#pragma unroll
        for (int j = 0; j < 16; j++) {
            ulonglong2 hv = *reinterpret_cast<const ulonglong2*>(hb + (j * 4 + seg) * 4);
            FMA2(acc0, w[j].x, hv.x);
            FMA2(acc1, w[j].y, hv.y);
        }
        float a0, a1, a2, a3;
        UNPACK2(a0, a1, acc0);
        UNPACK2(a2, a3, acc1);
        float acc = (a0 + a1) + (a2 + a3);
        acc += __shfl_xor_sync(0xffffffffu, acc, 1);
        acc += __shfl_xor_sync(0xffffffffu, acc, 2);
        if (seg == 0) s_gates[r_local] = acc + gin;
        if (seg == 0 && t + 1 < S_LEN)
            gin = G[(size_t)(t + 1) * (4 * H2) + row];  /* prefetch next step */
        __syncthreads();

        if (tid < 32) {
            float gi = s_gates[tid * 4 + 0];
            float gf = s_gates[tid * 4 + 1];
            float gg = s_gates[tid * 4 + 2];
            float go = s_gates[tid * 4 + 3];
            c = sigf(gf) * c + sigf(gi) * tanhf(gg);
            float h = sigf(go) * tanhf(c);
            int outrow = d ? (S_LEN - 1 - t) : t;
            g_lstm_out[(size_t)outrow * HH + d * H2 + b * 32 + tid] = h;

            if (t + 1 < S_LEN) {
                int nb = (t + 1) & 1;
#pragma unroll
                for (int p = 0; p < NBC; p++)
                    asm volatile("st.shared::cluster.f32 [%0], %1;"
                                 :: "r"(rdst[nb][p]), "f"(h) : "memory");
            }
        }
        /* release(my stores) -> all-cluster -> acquire(peer stores) */
        asm volatile("barrier.cluster.arrive.aligned;" ::: "memory");
        asm volatile("barrier.cluster.wait.aligned;" ::: "memory");
    }
}

/* ------------------- log_softmax over 64 tags (one warp per word) --------- */
__global__ void logsoftmax_kernel(float* __restrict__ out) {
    int gt = blockIdx.x * blockDim.x + threadIdx.x;
    int warp = gt >> 5;
    int lane = gt & 31;
    if (warp >= S_LEN) return;
    const float* l = g_logits + (size_t)warp * T_TAGS;
    float a = l[lane], b = l[lane + 32];
    float m = fmaxf(a, b);
#pragma unroll
    for (int o = 16; o > 0; o >>= 1) m = fmaxf(m, __shfl_xor_sync(0xffffffffu, m, o));
    float s = expf(a - m) + expf(b - m);
#pragma unroll
    for (int o = 16; o > 0; o >>= 1) s += __shfl_xor_sync(0xffffffffu, s, o);
    float lse = m + logf(s);
    out[(size_t)warp * T_TAGS + lane] = a - lse;
    out[(size_t)warp * T_TAGS + lane + 32] = b - lse;
}

/* ------------------- launcher --------------------------------------------- */
extern "C" void kernel_launch(void* const* d_in, const int* in_sizes, int n_in,
                              void* d_out, int out_size) {
    const int*   sentence  = (const int*)d_in[0];
    const int*   charsets  = (const int*)d_in[1];
    const int*   lengths   = (const int*)d_in[2];
    const float* word_emb  = (const float*)d_in[3];
    const float* char_emb  = (const float*)d_in[4];
    const float* cWih      = (const float*)d_in[5];
    const float* cWhh      = (const float*)d_in[6];
    const float* cb        = (const float*)d_in[7];
    const float* fWih      = (const float*)d_in[8];
    const float* fWhh      = (const float*)d_in[9];
    const float* fb        = (const float*)d_in[10];
    const float* bWih      = (const float*)d_in[11];
    const float* bWhh      = (const float*)d_in[12];
    const float* bb        = (const float*)d_in[13];
    const float* outW      = (const float*)d_in[14];
    const float* outb      = (const float*)d_in[15];
    float* out = (float*)d_out;

    void *pXc, *pIdx, *pGates, *pHc, *pEmb, *pGf, *pGb, *pLout, *pLog;
    cudaGetSymbolAddress(&pXc, g_Xc);
    cudaGetSymbolAddress(&pIdx, g_charidx);
    cudaGetSymbolAddress(&pGates, g_gates);
    cudaGetSymbolAddress(&pHc, g_Hc);
    cudaGetSymbolAddress(&pEmb, g_embeds);
    cudaGetSymbolAddress(&pGf, g_Gf);
    cudaGetSymbolAddress(&pGb, g_Gb);
    cudaGetSymbolAddress(&pLout, g_lstm_out);
    cudaGetSymbolAddress(&pLog, g_logits);

    /* reset per-launch state (graph-replay determinism) */
    init_state<<<2048, 256>>>();

    /* char LSTM input projection for all (t,w): gather + GEMM */
    build_charidx<<<(LCC * S_LEN + 255) / 256, 256>>>(charsets);
    gemm_tn<<<dim3(4 * HC / 64, LCC * S_LEN / 64), 256>>>(
        char_emb, DC, cWih, cb, (float*)pXc,
        LCC * S_LEN, 4 * HC, DC, (const int*)pIdx, 0);

    /* char LSTM: 16 time steps, batched over S */
    for (int t = 0; t < LCC; t++) {
        gemm_tn<<<dim3(4 * HC / 64, S_LEN / 64), 256>>>(
            (const float*)pHc, HC, cWhh, nullptr, (float*)pGates,
            S_LEN, 4 * HC, HC, nullptr, 0);
        char_update<<<S_LEN * HC / 256, 256>>>(lengths, t);
    }

    /* embeds + main input projections */
    build_embeds<<<S_LEN * KIN / 256, 256>>>(sentence, word_emb);
    gemm_tn<<<dim3(4 * H2 / 64, S_LEN / 64), 256>>>(
        (const float*)pEmb, KIN, fWih, fb, (float*)pGf,
        S_LEN, 4 * H2, KIN, nullptr, 0);
    gemm_tn<<<dim3(4 * H2 / 64, S_LEN / 64), 256>>>(
        (const float*)pEmb, KIN, bWih, bb, (float*)pGb,
        S_LEN, 4 * H2, KIN, nullptr, 1);

    /* sequential bidirectional recurrence: 2 clusters of 8 CTAs */
    recurrent_cluster<<<2 * NBC, RT2>>>(fWhh, bWhh);

    /* output projection + log_softmax */
    gemm_tn<<<dim3(T_TAGS / 64, S_LEN / 64), 256>>>(
        (const float*)pLout, HH, outW, outb, (float*)pLog,
        S_LEN, T_TAGS, HH, nullptr, 0);
    logsoftmax_kernel<<<(S_LEN * 32 + 255) / 256, 256>>>(out);
}

// round 5
// speedup vs baseline: 1.9396x; 1.2114x over previous
#include <cuda_runtime.h>
#include <math.h>
#include <stdint.h>

#define S_LEN 8192
#define LCC   16
#define DW    256
#define DC    64
#define HC    128
#define HH    512
#define T_TAGS 64
#define H2    256
#define KIN   384      /* HC + DW */
#define NBC   8        /* CTAs per direction (one portable cluster) */
#define RT2   512

/* ------------------- scratch (device globals; no allocation) ------------- */
__device__ float g_Xc[(size_t)LCC * S_LEN * 4 * HC];
__device__ int   g_charidx[LCC * S_LEN];
__device__ float g_gates[S_LEN * 4 * HC];
__device__ float g_Hc[S_LEN * HC];
__device__ float g_Cc[S_LEN * HC];
__device__ float g_charfeat[S_LEN * HC];
__device__ float g_embeds[S_LEN * KIN];
__device__ float g_Gf[(size_t)S_LEN * 4 * H2];
__device__ float g_Gb[(size_t)S_LEN * 4 * H2];
__device__ float g_lstm_out[S_LEN * HH];
__device__ float g_logits[S_LEN * T_TAGS];

__device__ __forceinline__ float sigf(float x) { return 1.0f / (1.0f + expf(-x)); }

/* ---- PTX helpers ---- */
__device__ __forceinline__ uint32_t smem_u32(const void* p) {
    uint32_t a;
    asm("{ .reg .u64 t; cvta.to.shared.u64 t, %1; cvt.u32.u64 %0, t; }" : "=r"(a) : "l"(p));
    return a;
}
__device__ __forceinline__ uint32_t mapa_rank(uint32_t addr, uint32_t rank) {
    uint32_t r;
    asm("mapa.shared::cluster.u32 %0, %1, %2;" : "=r"(r) : "r"(addr), "r"(rank));
    return r;
}
__device__ __forceinline__ void mbar_wait_acq(uint32_t mbar, uint32_t parity) {
    uint32_t done;
    asm volatile(
        "{\n\t.reg .pred p;\n\t"
        "mbarrier.try_wait.parity.acquire.cluster.shared::cta.b64 p, [%1], %2;\n\t"
        "selp.b32 %0, 1, 0, p;\n\t}"
        : "=r"(done) : "r"(mbar), "r"(parity) : "memory");
    while (!done) {
        asm volatile(
            "{\n\t.reg .pred p;\n\t"
            "mbarrier.try_wait.parity.acquire.cluster.shared::cta.b64 p, [%1], %2, 0x989680;\n\t"
            "selp.b32 %0, 1, 0, p;\n\t}"
            : "=r"(done) : "r"(mbar), "r"(parity) : "memory");
    }
}
__device__ __forceinline__ void mbar_arm(uint32_t mbar, uint32_t tx) {
    asm volatile("mbarrier.arrive.expect_tx.shared::cta.b64 _, [%0], %1;"
                 :: "r"(mbar), "r"(tx) : "memory");
}
__device__ __forceinline__ void st_async_b64(uint32_t raddr, unsigned long long v,
                                             uint32_t rmbar) {
    asm volatile("st.async.shared::cluster.mbarrier::complete_tx::bytes.b64 [%0], %1, [%2];"
                 :: "r"(raddr), "l"(v), "r"(rmbar) : "memory");
}
#define FMA2(acc, a, b) asm("fma.rn.f32x2 %0, %1, %2, %0;" : "+l"(acc) : "l"(a), "l"(b))
#define UNPACK2(lo, hi, v) asm("mov.b64 {%0,%1}, %2;" : "=f"(lo), "=f"(hi) : "l"(v))

/* ------------------- init: must run every launch (graph determinism) ----- */
__global__ void init_state() {
    int idx = blockIdx.x * blockDim.x + threadIdx.x;
    int stride = gridDim.x * blockDim.x;
    for (int i = idx; i < S_LEN * HC; i += stride) {
        g_Hc[i] = 0.0f;
        g_Cc[i] = 0.0f;
    }
}

__global__ void build_charidx(const int* __restrict__ charsets) {
    int idx = blockIdx.x * blockDim.x + threadIdx.x;
    if (idx >= LCC * S_LEN) return;
    int t = idx / S_LEN;
    int w = idx - t * S_LEN;
    g_charidx[idx] = charsets[w * LCC + t];
}

/* ------------------- generic fp32 GEMM ------------------------------------ */
__global__ void __launch_bounds__(256) gemm_tn(
    const float* __restrict__ A, int lda,
    const float* __restrict__ B,
    const float* __restrict__ bias,
    float* __restrict__ C, int M, int N, int K,
    const int* __restrict__ gidx, int rev)
{
    __shared__ float4 As4[16 * 16];
    __shared__ float4 Bs4[16 * 16];
    float* As = (float*)As4;
    float* Bs = (float*)Bs4;

    int tid = threadIdx.x;
    int m0 = blockIdx.y * 64, n0 = blockIdx.x * 64;
    int lm = tid >> 2;
    int kq = tid & 3;

    int mg = m0 + lm;
    int arow = gidx ? gidx[mg] : (rev ? (M - 1 - mg) : mg);
    const float* Ap = A + (size_t)arow * lda;
    const float* Bp = B + (size_t)(n0 + lm) * K;

    int ty = tid >> 4, tx = tid & 15;
    float acc[4][4];
#pragma unroll
    for (int i = 0; i < 4; i++)
#pragma unroll
        for (int j = 0; j < 4; j++) acc[i][j] = 0.0f;

    for (int k0 = 0; k0 < K; k0 += 16) {
        float4 a = *(const float4*)(Ap + k0 + kq * 4);
        float4 b = *(const float4*)(Bp + k0 + kq * 4);
        __syncthreads();
        As[(kq * 4 + 0) * 64 + lm] = a.x;
        As[(kq * 4 + 1) * 64 + lm] = a.y;
        As[(kq * 4 + 2) * 64 + lm] = a.z;
        As[(kq * 4 + 3) * 64 + lm] = a.w;
        Bs[(kq * 4 + 0) * 64 + lm] = b.x;
        Bs[(kq * 4 + 1) * 64 + lm] = b.y;
        Bs[(kq * 4 + 2) * 64 + lm] = b.z;
        Bs[(kq * 4 + 3) * 64 + lm] = b.w;
        __syncthreads();
#pragma unroll
        for (int kk = 0; kk < 16; kk++) {
            float4 av = As4[kk * 16 + ty];
            float4 bv = Bs4[kk * 16 + tx];
            acc[0][0] += av.x * bv.x; acc[0][1] += av.x * bv.y;
            acc[0][2] += av.x * bv.z; acc[0][3] += av.x * bv.w;
            acc[1][0] += av.y * bv.x; acc[1][1] += av.y * bv.y;
            acc[1][2] += av.y * bv.z; acc[1][3] += av.y * bv.w;
            acc[2][0] += av.z * bv.x; acc[2][1] += av.z * bv.y;
            acc[2][2] += av.z * bv.z; acc[2][3] += av.z * bv.w;
            acc[3][0] += av.w * bv.x; acc[3][1] += av.w * bv.y;
            acc[3][2] += av.w * bv.z; acc[3][3] += av.w * bv.w;
        }
    }
#pragma unroll
    for (int i = 0; i < 4; i++) {
        int m = m0 + ty * 4 + i;
        int n = n0 + tx * 4;
        float4 o;
        o.x = acc[i][0]; o.y = acc[i][1]; o.z = acc[i][2]; o.w = acc[i][3];
        if (bias) {
            o.x += bias[n + 0]; o.y += bias[n + 1];
            o.z += bias[n + 2]; o.w += bias[n + 3];
        }
        *(float4*)(C + (size_t)m * N + n) = o;
    }
}

/* ------------------- char LSTM pointwise update --------------------------- */
__global__ void char_update(const int* __restrict__ lengths, int t) {
    int idx = blockIdx.x * blockDim.x + threadIdx.x;
    if (idx >= S_LEN * HC) return;
    int w = idx / HC, u = idx - w * HC;
    const float* xrow = g_Xc + ((size_t)t * S_LEN + w) * (4 * HC);
    const float* grow = g_gates + (size_t)w * (4 * HC);
    float gi = grow[0 * HC + u] + xrow[0 * HC + u];
    float gf = grow[1 * HC + u] + xrow[1 * HC + u];
    float gg = grow[2 * HC + u] + xrow[2 * HC + u];
    float go = grow[3 * HC + u] + xrow[3 * HC + u];
    float c = g_Cc[idx];
    c = sigf(gf) * c + sigf(gi) * tanhf(gg);
    float h = sigf(go) * tanhf(c);
    g_Cc[idx] = c;
    g_Hc[idx] = h;
    if (t == lengths[w] - 1) g_charfeat[idx] = h;
}

/* ------------------- embeds = [charfeat | word_emb[sentence]] ------------- */
__global__ void build_embeds(const int* __restrict__ sentence,
                             const float* __restrict__ word_emb) {
    int idx = blockIdx.x * blockDim.x + threadIdx.x;
    if (idx >= S_LEN * KIN) return;
    int w = idx / KIN, j = idx - w * KIN;
    float v;
    if (j < HC) v = g_charfeat[w * HC + j];
    else        v = word_emb[(size_t)sentence[w] * DW + (j - HC)];
    g_embeds[idx] = v;
}

/* ------------------- barrier-free cluster recurrence ----------------------
 * 2 clusters of 8 CTAs (one per direction), 512 threads each.
 * Each WARP owns 2 h-units end-to-end: dot over 8 gate rows (k split by 4),
 * xor-shfl reduce, idx-shfl gather, redundant in-lane gate math, then ONE
 * lane pushes a packed b64 (2 h values) to all 8 CTAs' smem via
 * st.async.mbarrier::complete_tx. Consumers wait on local mbarrier parity
 * (expect_tx = 1024 B = full 256-float h). No __syncthreads / cluster
 * barrier / L1 flush anywhere in the step loop.
 * Buffer-reuse safety: a peer advances past step t only after ALL 16 warps
 * of every CTA delivered (tx is CTA-global), which implies every warp
 * finished reading the buffer that step t+1's stores overwrite.           */
__global__ void __launch_bounds__(RT2, 1) __cluster_dims__(NBC, 1, 1)
recurrent_cluster(const float* __restrict__ WhhF, const float* __restrict__ WhhB)
{
    __shared__ __align__(16) float s_h[2][H2];
    __shared__ __align__(8) unsigned long long s_mbar[2];

    int tid = threadIdx.x;
    int wid = tid >> 5;
    int lane = tid & 31;
    int d = blockIdx.x >> 3;
    int b = blockIdx.x & 7;
    const float* Whh = d ? WhhB : WhhF;
    const float* G = d ? g_Gb : g_Gf;

    int seg = lane & 3;            /* k-split 0..3           */
    int r_l = lane >> 2;           /* 0..7: j = r_l>>2, gk = r_l&3 */
    int j = r_l >> 2;
    int gk = r_l & 3;
    int u = b * 32 + wid * 2 + j;  /* global h-unit of this lane */
    int row = gk * H2 + u;         /* gate row                   */

    /* 64 weights per thread, packed f32x2 */
    ulonglong2 w[16];
    const float* wrow = Whh + (size_t)row * H2;
#pragma unroll
    for (int jj = 0; jj < 16; jj++)
        w[jj] = *reinterpret_cast<const ulonglong2*>(wrow + (jj * 4 + seg) * 4);

    if (tid < H2) { s_h[0][tid] = 0.0f; s_h[1][tid] = 0.0f; }

    uint32_t mb0 = smem_u32(&s_mbar[0]);
    uint32_t mb1 = smem_u32(&s_mbar[1]);
    if (tid == 0) {
        asm volatile("mbarrier.init.shared.b64 [%0], %1;" :: "r"(mb0), "r"(1) : "memory");
        asm volatile("mbarrier.init.shared.b64 [%0], %1;" :: "r"(mb1), "r"(1) : "memory");
        mbar_arm(mb0, 1024);   /* phase 0: deliveries at end of step 1 */
        mbar_arm(mb1, 1024);   /* phase 0: deliveries at end of step 0 */
        asm volatile("fence.mbarrier_init.release.cluster;" ::: "memory");
    }
    __syncthreads();
    asm volatile("barrier.cluster.arrive.aligned;" ::: "memory");
    asm volatile("barrier.cluster.wait.aligned;" ::: "memory");

    uint32_t hbuf0 = smem_u32(&s_h[0][0]);
    uint32_t hbuf1 = smem_u32(&s_h[1][0]);
    uint32_t ph0 = 0, ph1 = 0;

    float c = 0.0f;
    float gin = 0.0f;
    if (seg == 0) gin = G[row];    /* prefetch t=0 */

    for (int t = 0; t < S_LEN; t++) {
        int idx = t & 1;
        if (t > 0) {
            uint32_t mb = idx ? mb1 : mb0;
            uint32_t ph = idx ? ph1 : ph0;
            mbar_wait_acq(mb, ph);
            if (idx) ph1 ^= 1; else ph0 ^= 1;
            if (tid == 0) mbar_arm(mb, 1024);   /* re-arm for step t+2 */
        }

        const float* hb = s_h[idx];
        unsigned long long acc0 = 0ull, acc1 = 0ull;
#pragma unroll
        for (int jj = 0; jj < 16; jj++) {
            ulonglong2 hv = *reinterpret_cast<const ulonglong2*>(hb + (jj * 4 + seg) * 4);
            FMA2(acc0, w[jj].x, hv.x);
            FMA2(acc1, w[jj].y, hv.y);
        }
        float a0, a1, a2, a3;
        UNPACK2(a0, a1, acc0);
        UNPACK2(a2, a3, acc1);
        float acc = (a0 + a1) + (a2 + a3);
        acc += __shfl_xor_sync(0xffffffffu, acc, 1);
        acc += __shfl_xor_sync(0xffffffffu, acc, 2);
        if (seg == 0) acc += gin;              /* +input-proj gate */

        /* gather 4 gates of this lane's unit (sources are seg0 lanes) */
        int base = lane & 16;
        float gi = __shfl_sync(0xffffffffu, acc, base + 0);
        float gf = __shfl_sync(0xffffffffu, acc, base + 4);
        float gg = __shfl_sync(0xffffffffu, acc, base + 8);
        float go = __shfl_sync(0xffffffffu, acc, base + 12);

        c = sigf(gf) * c + sigf(gi) * tanhf(gg);
        float h = sigf(go) * tanhf(c);

        if (seg == 0 && t + 1 < S_LEN)
            gin = G[(size_t)(t + 1) * (4 * H2) + row];  /* prefetch next */

        if ((lane & 15) == 0) {                /* lanes 0,16: units u0,u1 */
            int outrow = d ? (S_LEN - 1 - t) : t;
            g_lstm_out[(size_t)outrow * HH + d * H2 + u] = h;
        }
        float h1 = __shfl_sync(0xffffffffu, h, 16);

        if (lane == 0 && t + 1 < S_LEN) {
            unsigned long long pv;
            asm("mov.b64 %0, {%1,%2};" : "=l"(pv) : "f"(h), "f"(h1));
            uint32_t dst = (idx ? hbuf0 : hbuf1) + (uint32_t)(b * 32 + wid * 2) * 4u;
            uint32_t mbn = idx ? mb0 : mb1;    /* mbar[(t+1)&1] */
#pragma unroll
            for (int p = 0; p < NBC; p++) {
                uint32_t ra = mapa_rank(dst, (uint32_t)p);
                uint32_t rb = mapa_rank(mbn, (uint32_t)p);
                st_async_b64(ra, pv, rb);
            }
        }
    }

    asm volatile("barrier.cluster.arrive.aligned;" ::: "memory");
    asm volatile("barrier.cluster.wait.aligned;" ::: "memory");
}

/* ------------------- log_softmax over 64 tags (one warp per word) --------- */
__global__ void logsoftmax_kernel(float* __restrict__ out) {
    int gt = blockIdx.x * blockDim.x + threadIdx.x;
    int warp = gt >> 5;
    int lane = gt & 31;
    if (warp >= S_LEN) return;
    const float* l = g_logits + (size_t)warp * T_TAGS;
    float a = l[lane], b = l[lane + 32];
    float m = fmaxf(a, b);
#pragma unroll
    for (int o = 16; o > 0; o >>= 1) m = fmaxf(m, __shfl_xor_sync(0xffffffffu, m, o));
    float s = expf(a - m) + expf(b - m);
#pragma unroll
    for (int o = 16; o > 0; o >>= 1) s += __shfl_xor_sync(0xffffffffu, s, o);
    float lse = m + logf(s);
    out[(size_t)warp * T_TAGS + lane] = a - lse;
    out[(size_t)warp * T_TAGS + lane + 32] = b - lse;
}

/* ------------------- launcher --------------------------------------------- */
extern "C" void kernel_launch(void* const* d_in, const int* in_sizes, int n_in,
                              void* d_out, int out_size) {
    const int*   sentence  = (const int*)d_in[0];
    const int*   charsets  = (const int*)d_in[1];
    const int*   lengths   = (const int*)d_in[2];
    const float* word_emb  = (const float*)d_in[3];
    const float* char_emb  = (const float*)d_in[4];
    const float* cWih      = (const float*)d_in[5];
    const float* cWhh      = (const float*)d_in[6];
    const float* cb        = (const float*)d_in[7];
    const float* fWih      = (const float*)d_in[8];
    const float* fWhh      = (const float*)d_in[9];
    const float* fb        = (const float*)d_in[10];
    const float* bWih      = (const float*)d_in[11];
    const float* bWhh      = (const float*)d_in[12];
    const float* bb        = (const float*)d_in[13];
    const float* outW      = (const float*)d_in[14];
    const float* outb      = (const float*)d_in[15];
    float* out = (float*)d_out;

    void *pXc, *pIdx, *pGates, *pHc, *pEmb, *pGf, *pGb, *pLout, *pLog;
    cudaGetSymbolAddress(&pXc, g_Xc);
    cudaGetSymbolAddress(&pIdx, g_charidx);
    cudaGetSymbolAddress(&pGates, g_gates);
    cudaGetSymbolAddress(&pHc, g_Hc);
    cudaGetSymbolAddress(&pEmb, g_embeds);
    cudaGetSymbolAddress(&pGf, g_Gf);
    cudaGetSymbolAddress(&pGb, g_Gb);
    cudaGetSymbolAddress(&pLout, g_lstm_out);
    cudaGetSymbolAddress(&pLog, g_logits);

    /* reset per-launch state (graph-replay determinism) */
    init_state<<<2048, 256>>>();

    /* char LSTM input projection for all (t,w): gather + GEMM */
    build_charidx<<<(LCC * S_LEN + 255) / 256, 256>>>(charsets);
    gemm_tn<<<dim3(4 * HC / 64, LCC * S_LEN / 64), 256>>>(
        char_emb, DC, cWih, cb, (float*)pXc,
        LCC * S_LEN, 4 * HC, DC, (const int*)pIdx, 0);

    /* char LSTM: 16 time steps, batched over S */
    for (int t = 0; t < LCC; t++) {
        gemm_tn<<<dim3(4 * HC / 64, S_LEN / 64), 256>>>(
            (const float*)pHc, HC, cWhh, nullptr, (float*)pGates,
            S_LEN, 4 * HC, HC, nullptr, 0);
        char_update<<<S_LEN * HC / 256, 256>>>(lengths, t);
    }

    /* embeds + main input projections */
    build_embeds<<<S_LEN * KIN / 256, 256>>>(sentence, word_emb);
    gemm_tn<<<dim3(4 * H2 / 64, S_LEN / 64), 256>>>(
        (const float*)pEmb, KIN, fWih, fb, (float*)pGf,
        S_LEN, 4 * H2, KIN, nullptr, 0);
    gemm_tn<<<dim3(4 * H2 / 64, S_LEN / 64), 256>>>(
        (const float*)pEmb, KIN, bWih, bb, (float*)pGb,
        S_LEN, 4 * H2, KIN, nullptr, 1);

    /* sequential bidirectional recurrence: 2 clusters of 8 CTAs */
    recurrent_cluster<<<2 * NBC, RT2>>>(fWhh, bWhh);

    /* output projection + log_softmax */
    gemm_tn<<<dim3(T_TAGS / 64, S_LEN / 64), 256>>>(
        (const float*)pLout, HH, outW, outb, (float*)pLog,
        S_LEN, T_TAGS, HH, nullptr, 0);
    logsoftmax_kernel<<<(S_LEN * 32 + 255) / 256, 256>>>(out);
}